// round 8
// baseline (speedup 1.0000x reference)
#include <cuda_runtime.h>
#include <math.h>

// B=64, N=17, T=512, C=64, H=4, DK=16
#define NB 64
#define NN 17
#define NT 512
#define NC 64

typedef unsigned long long u64;

// Intermediate GAT output g[b,n,t,c] (flat per (b,n): t*64+c), 142.6 MB scratch.
__device__ float g_buf[(size_t)NB * NN * NT * NC];

// ---- packed fp32x2 helpers (Blackwell) ----
__device__ __forceinline__ u64 pack2(float lo, float hi) {
    u64 r;
    asm("mov.b64 %0,{%1,%2};" : "=l"(r) : "f"(lo), "f"(hi));
    return r;
}
__device__ __forceinline__ void unpack2(u64 v, float& lo, float& hi) {
    asm("mov.b64 {%0,%1},%2;" : "=f"(lo), "=f"(hi) : "l"(v));
}
__device__ __forceinline__ u64 fma2(u64 a, u64 b, u64 c) {
    u64 d;
    asm("fma.rn.f32x2 %0,%1,%2,%3;" : "=l"(d) : "l"(a), "l"(b), "l"(c));
    return d;
}
__device__ __forceinline__ u64 mul2(u64 a, u64 b) {
    u64 d;
    asm("mul.rn.f32x2 %0,%1,%2;" : "=l"(d) : "l"(a), "l"(b));
    return d;
}
__device__ __forceinline__ u64 add2(u64 a, u64 b) {
    u64 d;
    asm("add.rn.f32x2 %0,%1,%2;" : "=l"(d) : "l"(a), "l"(b));
    return d;
}
__device__ __forceinline__ u64 abs2(u64 a) {
    u64 d;
    asm("and.b64 %0,%1,0x7FFFFFFF7FFFFFFF;" : "=l"(d) : "l"(a));
    return d;
}
__device__ __forceinline__ u64 neg2(u64 a) {
    u64 d;
    asm("xor.b64 %0,%1,0x8000000080000000;" : "=l"(d) : "l"(a));
    return d;
}
__device__ __forceinline__ float rcpf(float x) {
    float r;
    asm("rcp.approx.f32 %0,%1;" : "=f"(r) : "f"(x));
    return r;
}
#define KP2(f) pack2(f, f)

// Paired GELU: erf via A&S 7.1.28 (1 - poly6^-16), |abs err|<=3e-7.
// One MUFU.RCP per lane, no EX2.
__device__ __forceinline__ u64 gelu2(u64 v2) {
    u64 av = abs2(v2);
    u64 z  = mul2(av, KP2(0.70710678118654752440f));
    u64 p  = fma2(KP2(0.0000430638f), z, KP2(0.0002765672f));
    p = fma2(p, z, KP2(0.0001520143f));
    p = fma2(p, z, KP2(0.0092705272f));
    p = fma2(p, z, KP2(0.0422820123f));
    p = fma2(p, z, KP2(0.0705230784f));
    p = fma2(p, z, KP2(1.0f));
    p = mul2(p, p); p = mul2(p, p); p = mul2(p, p); p = mul2(p, p);  // p^16
    float plo, phi;
    unpack2(p, plo, phi);
    u64 r = pack2(rcpf(plo), rcpf(phi));     // 1/p^16 -> 1-erf
    u64 t = add2(v2, av);                    // v + |v|
    u64 m = mul2(av, r);                     // |v| * (1-erf)
    u64 s = add2(t, neg2(m));
    return mul2(s, KP2(0.5f));               // 0.5*(v + |v|*erf)
}

// =====================================================================
// K1: GAT.  One block per (b, t-chunk of 8).  grid 4096, 544 threads.
// h lives in registers (16 floats/thread); no hs array.
// No-max softmax (values bounded; masked terms underflow to exactly 0).
// smem floats: Wt 4224 | xs 8976 | av 32 | bias 289 |
//              ss/ts/rowR/scl 544 each  (= 15697 ~ 62.8KB) -> 3 blk/SM
// xs addr(n,f) = n*528 + (f>>6)*66 + (f&63)   (f = tl*64 + c)
// =====================================================================
extern "C" __global__ void __launch_bounds__(544, 3)
gat_kernel(const float* __restrict__ x, const int* __restrict__ adj,
           const float* __restrict__ W, const float* __restrict__ a)
{
    extern __shared__ float sm[];
    float* Wt   = sm;            // transposed: Wt[c*66 + o] = W[o][c]
    float* xs   = Wt + 4224;
    float* av   = xs + 8976;
    float* bias = av + 32;
    float* ss   = bias + 289;
    float* ts   = ss + 544;
    float* rowR = ts + 544;
    float* scl  = rowR + 544;

    const int tid = threadIdx.x;
    const int b   = blockIdx.x >> 6;
    const int t0  = (blockIdx.x & 63) * 8;

    // ---- P0: loads ----
    for (int i = tid; i < 4096; i += 544) {
        int o = i >> 6, c = i & 63;
        Wt[c * 66 + o] = W[i];
    }
    {   // x slab as float2: 4352 float2, 8 iters
        const float2* xb2 = (const float2*)x + (size_t)b * 278528 + t0 * 32;
        #pragma unroll
        for (int k = 0; k < 8; k++) {
            int i = tid + k * 544;
            int n = i >> 8, rem = i & 255;     // 256 float2 per node
            int tl = rem >> 5, cpl = rem & 31;
            float2 v = xb2[(size_t)n * 16384 + tl * 32 + cpl];
            ((float2*)xs)[n * 264 + tl * 33 + cpl] = v;
        }
    }
    if (tid < 32) av[tid] = a[tid];
    if (tid < 289)
        bias[tid] = (adj[b * 289 + tid] == 0) ? -1e9f : 0.0f;
    __syncthreads();

    // ---- P1: h = h0 @ W^T ; packed f32x2, c in pairs, h in registers ----
    const int og = tid & 15;     // output pairs (2og,2og+1) and (+32,+33)
    const int pg = tid >> 4;     // p = pg + 34*j, p = tl*17+n
    u64 acc[2][4];
    int pb[4];
    {
        #pragma unroll
        for (int j = 0; j < 4; j++) {
            int p = pg + 34 * j;
            int n = p % 17, tl = p / 17;
            pb[j] = n * 528 + tl * 66;
            acc[0][j] = 0ULL; acc[1][j] = 0ULL;
        }
        const u64* w0p = (const u64*)(Wt + 2 * og);
        const u64* w1p = (const u64*)(Wt + 2 * og + 32);
        #pragma unroll 4
        for (int c = 0; c < 64; c += 2) {
            u64 w0a = w0p[c * 33],       w1a = w1p[c * 33];
            u64 w0b = w0p[(c + 1) * 33], w1b = w1p[(c + 1) * 33];
            #pragma unroll
            for (int j = 0; j < 4; j++) {
                float2 xv = *(const float2*)&xs[pb[j] + c];
                u64 xa = pack2(xv.x, xv.x);
                u64 xb = pack2(xv.y, xv.y);
                acc[0][j] = fma2(w0a, xa, acc[0][j]);
                acc[1][j] = fma2(w1a, xa, acc[1][j]);
                acc[0][j] = fma2(w0b, xb, acc[0][j]);
                acc[1][j] = fma2(w1b, xb, acc[1][j]);
            }
        }
    }

    // ---- P2: s,t via in-warp 8-lane reductions of register h ----
    {
        const int h0 = og >> 3;            // head of pair (2og,2og+1); +2 for hi
        const int d0 = 2 * (og & 7);       // a-index within head
        const float aS0 = av[d0],      aS1 = av[d0 + 1];
        const float aT0 = av[16 + d0], aT1 = av[17 + d0];
        #pragma unroll
        for (int j = 0; j < 4; j++) {
            float hlo0, hhi0, hlo1, hhi1;
            unpack2(acc[0][j], hlo0, hhi0);
            unpack2(acc[1][j], hlo1, hhi1);
            float sA = fmaf(hlo0, aS0, hhi0 * aS1);
            float tA = fmaf(hlo0, aT0, hhi0 * aT1);
            float sB = fmaf(hlo1, aS0, hhi1 * aS1);
            float tB = fmaf(hlo1, aT0, hhi1 * aT1);
            #pragma unroll
            for (int w = 4; w; w >>= 1) {
                sA += __shfl_xor_sync(0xffffffffu, sA, w);
                tA += __shfl_xor_sync(0xffffffffu, tA, w);
                sB += __shfl_xor_sync(0xffffffffu, sB, w);
                tB += __shfl_xor_sync(0xffffffffu, tB, w);
            }
            if ((og & 7) == 0) {
                int p = pg + 34 * j;
                ss[p * 4 + h0]     = sA;
                ss[p * 4 + h0 + 2] = sB;
                ts[p * 4 + h0]     = tA;
                ts[p * 4 + h0 + 2] = tB;
            }
        }
    }
    __syncthreads();

    // ---- P3: row sums S_i (no max subtraction; masked -> exp underflows to 0)
    {
        int q = tid;
        int h = q & 3, p = q >> 2;
        int i = p % 17, tl = p / 17;
        float sv = ss[q];
        const float* tsr = ts + (tl * 17) * 4 + h;
        const float* br  = bias + i * 17;
        float S = 0.0f;
        #pragma unroll
        for (int j = 0; j < 17; j++) {
            float e = sv + tsr[j * 4];
            e = (e > 0.0f) ? e : 0.2f * e;
            S += __expf(e + br[j]);
        }
        // S==0 only if row fully masked: reference softmax -> uniform 1/17.
        rowR[q] = (S > 0.0f) ? 1.0f / S : -1.0f;
    }
    __syncthreads();

    // ---- P4: scale[tl,j,h] = sum_i alpha[i,j,h] ----
    {
        int q = tid;
        int h = q & 3, p = q >> 2;
        int jj = p % 17, tl = p / 17;
        float tv = ts[q];
        float acc4 = 0.0f;
        #pragma unroll
        for (int i = 0; i < 17; i++) {
            int qi = (tl * 17 + i) * 4 + h;
            float e = ss[qi] + tv;
            e = (e > 0.0f) ? e : 0.2f * e;
            float R = rowR[qi];
            float term = __expf(e + bias[i * 17 + jj]) * R;
            if (R < 0.0f) term = 0.05882352941176470588f;   // 1/17
            acc4 += term;
        }
        scl[q] = acc4;
    }
    __syncthreads();

    // ---- P5: g = h*scale + h0 -> g_buf directly from registers ----
    {
        const int h0 = og >> 3;
        float* gbase = g_buf + (size_t)b * 557056 + t0 * 64;
        #pragma unroll
        for (int j = 0; j < 4; j++) {
            int p = pg + 34 * j;
            int n = p % 17, tl = p / 17;
            float sc0 = scl[(tl * 17 + n) * 4 + h0];
            float sc2 = scl[(tl * 17 + n) * 4 + h0 + 2];
            float hlo0, hhi0, hlo1, hhi1;
            unpack2(acc[0][j], hlo0, hhi0);
            unpack2(acc[1][j], hlo1, hhi1);
            float2 x0 = *(const float2*)&xs[pb[j] + 2 * og];
            float2 x1 = *(const float2*)&xs[pb[j] + 2 * og + 32];
            float2 g0, g1;
            g0.x = fmaf(hlo0, sc0, x0.x);
            g0.y = fmaf(hhi0, sc0, x0.y);
            g1.x = fmaf(hlo1, sc2, x1.x);
            g1.y = fmaf(hhi1, sc2, x1.y);
            int base = n * 32768 + tl * 64;
            *(float2*)(gbase + base + 2 * og)      = g0;
            *(float2*)(gbase + base + 2 * og + 32) = g1;
        }
    }
}

// =====================================================================
// K2: causal depthwise TCN x2 + transpose + permuted residual.
// Block = (b, tau-chunk of 8); 544 threads; each thread owns the row PAIR
// (2*tid, 2*tid+1) = same n, adjacent cc -> all math in f32x2, STG.64 out.
// smem floats: xs 17*518=8806 | pad 2 | gss 544*15 u64 = 16320 | cw 640
//              (= 25768 floats ~ 103.1 KB) -> 2 blocks/SM
// gss[pr*15+idx] (u64) lanes = (row 2pr, row 2pr+1), idx: g[tau0-6+idx]
// =====================================================================
extern "C" __global__ void __launch_bounds__(544, 2)
tcn_kernel(const float* __restrict__ x,
           const float* __restrict__ w1, const float* __restrict__ gamma1,
           const float* __restrict__ beta1,
           const float* __restrict__ w2, const float* __restrict__ gamma2,
           const float* __restrict__ beta2,
           float* __restrict__ out)
{
    extern __shared__ float sm[];
    float* xs  = sm;                   // [17][518]  x slab (residual source)
    u64*  gss  = (u64*)(sm + 8808);    // [544][15] interleaved halo pairs
    float* cw  = sm + 8808 + 16320;    // packed conv/BN params (640)

    const int tid  = threadIdx.x;
    const int bid  = blockIdx.x;
    const int tau0 = (bid & 63) * 8;
    const int b    = bid >> 6;

    // x slab: 17 n x 8 t x 64 c = 4352 float2, 8 iters
    {
        const float2* xb2 = (const float2*)x + (size_t)b * 278528 + tau0 * 32;
        #pragma unroll
        for (int k = 0; k < 8; k++) {
            int i = tid + k * 544;
            int n = i >> 8, rem = i & 255;     // 256 fl2 per node
            int kk = rem >> 5, cpl = rem & 31;
            float2 v = xb2[(size_t)n * 16384 + kk * 32 + cpl];
            *(float2*)&xs[n * 518 + kk * 64 + 2 * cpl] = v;
        }
    }
    for (int i = tid; i < 640; i += 544) {
        float v;
        if      (i < 192) v = w1[i];
        else if (i < 256) v = gamma1[i - 192];
        else if (i < 320) v = beta1[i - 256];
        else if (i < 512) v = w2[i - 320];
        else if (i < 576) v = gamma2[i - 512];
        else              v = beta2[i - 576];
        cw[i] = v;
    }
    // g halo: 1088 rows x 7 float2 (g[tau0-6 .. tau0+7]), exactly 14 iters.
    // Write interleaved: gss float lane = row&1.
    {
        const float2* gblk2 = (const float2*)(g_buf) + (size_t)b * 278528;
        const int toff = (tau0 - 6) >> 1;   // tau0-6 even
        float* gssf = (float*)gss;
        #pragma unroll
        for (int k = 0; k < 14; k++) {
            int i = tid + k * 544;
            int row = i / 7, jp = i - row * 7;
            int n = row >> 6, cc = row & 63;
            int tt0 = tau0 - 6 + 2 * jp;
            float2 v;
            if (tt0 >= 0)
                v = gblk2[n * 16384 + cc * 256 + toff + jp];
            else {
                v.x = 0.0f;
                v.y = (tt0 == -1 - 1) && false ? 0.0f : 0.0f;
                // tt0+1 could be 0 only if tt0==-1, impossible (tt0 even)
            }
            int pr = row >> 1, lane = row & 1;
            int fb = (pr * 15 + 2 * jp) * 2 + lane;
            gssf[fb]     = v.x;
            gssf[fb + 2] = v.y;
        }
    }
    __syncthreads();

    const float rsb = 0.9999950000374997f;   // 1/sqrt(1 + 1e-5)
    {
        const int pr  = tid;
        const int r0  = 2 * pr;
        const int n   = r0 >> 6, cc0 = r0 & 63, cc1 = cc0 + 1;
        const float gsa0 = cw[192 + cc0] * rsb, gsa1 = cw[192 + cc1] * rsb;
        const float gsb0 = cw[512 + cc0] * rsb, gsb1 = cw[512 + cc1] * rsb;
        const u64 A0p = pack2(cw[cc0 * 3 + 0] * gsa0, cw[cc1 * 3 + 0] * gsa1);
        const u64 A1p = pack2(cw[cc0 * 3 + 1] * gsa0, cw[cc1 * 3 + 1] * gsa1);
        const u64 A2p = pack2(cw[cc0 * 3 + 2] * gsa0, cw[cc1 * 3 + 2] * gsa1);
        const u64 B1p = pack2(cw[256 + cc0], cw[256 + cc1]);
        const u64 C0p = pack2(cw[320 + cc0 * 3 + 0] * gsb0,
                              cw[320 + cc1 * 3 + 0] * gsb1);
        const u64 C1p = pack2(cw[320 + cc0 * 3 + 1] * gsb0,
                              cw[320 + cc1 * 3 + 1] * gsb1);
        const u64 C2p = pack2(cw[320 + cc0 * 3 + 2] * gsb0,
                              cw[320 + cc1 * 3 + 2] * gsb1);
        const u64 B2p = pack2(cw[576 + cc0], cw[576 + cc1]);

        const int ns0 = r0 % 17,  cs0 = r0 / 17;
        const int r1  = r0 + 1;
        const int ns1 = r1 % 17,  cs1 = r1 / 17;
        float* orow = out + ((size_t)(b * NN + n) * 512 + tau0) * 64 + cc0;
        const u64* gr = gss + pr * 15;

        u64 gm2 = gr[0], gm1 = gr[1];
        u64 yw0 = 0ULL, yw1 = 0ULL, yw2 = 0ULL, yw3 = 0ULL;
        const bool zf = (tau0 == 0);
        #pragma unroll
        for (int j = -4; j < 8; j++) {
            u64 g0 = gr[j + 6];
            u64 V = fma2(A0p, gm2, B1p);
            V = fma2(A1p, gm1, V);
            V = fma2(A2p, g0, V);
            u64 Y = gelu2(V);
            if (zf && j < 0) Y = 0ULL;
            if (j >= 0) {
                u64 Wv = fma2(C0p, yw0, B2p);
                Wv = fma2(C1p, yw2, Wv);
                Wv = fma2(C2p, Y, Wv);
                u64 Z = gelu2(Wv);
                float rx0 = xs[ns0 * 518 + j * 64 + cs0];
                float rx1 = xs[ns1 * 518 + j * 64 + cs1];
                u64 O = add2(Z, pack2(rx0, rx1));
                *(u64*)(orow + j * 64) = O;
            }
            yw0 = yw1; yw1 = yw2; yw2 = yw3; yw3 = Y;
            gm2 = gm1; gm1 = g0;
        }
    }
}

// =====================================================================
extern "C" void kernel_launch(void* const* d_in, const int* in_sizes, int n_in,
                              void* d_out, int out_size)
{
    const float* x   = (const float*)d_in[0];
    const int*   adj = (const int*)  d_in[1];
    const float* W   = (const float*)d_in[2];
    const float* a   = (const float*)d_in[3];
    const float* w1  = (const float*)d_in[4];
    const float* g1  = (const float*)d_in[5];
    const float* b1  = (const float*)d_in[6];
    const float* w2  = (const float*)d_in[7];
    const float* g2  = (const float*)d_in[8];
    const float* b2  = (const float*)d_in[9];
    float* out = (float*)d_out;

    const size_t sm1 = (size_t)15697 * 4;   // 62.8 KB -> 3 blocks/SM
    const size_t sm2 = (size_t)25768 * 4;   // 103.1 KB -> 2 blocks/SM
    cudaFuncSetAttribute(gat_kernel, cudaFuncAttributeMaxDynamicSharedMemorySize, (int)sm1);
    cudaFuncSetAttribute(tcn_kernel, cudaFuncAttributeMaxDynamicSharedMemorySize, (int)sm2);

    gat_kernel<<<4096, 544, sm1>>>(x, adj, W, a);
    tcn_kernel<<<4096, 544, sm2>>>(x, w1, g1, b1, w2, g2, b2, out);
}